// round 7
// baseline (speedup 1.0000x reference)
#include <cuda_runtime.h>
#include <cuda_bf16.h>
#include <cuda_pipeline.h>
#include <math.h>

#define VOCAB 50000
#define D 256
#define Bn 128
#define Sn 64
#define Ln 32
#define Kn 32

// Scratch (device globals: allocation-free rule)
__device__ float  g_enc [Bn * Sn * D];          // enc_sents   (B,S,D)
__device__ float  g_encW[Bn * Sn * D];          // enc_sents@W (B,S,D)
__device__ float  g_keysV[Bn * Kn * D];         // keys@V      (B,K,D)
__device__ float  g_eK  [Bn * Sn * Kn];         // enc·keys    (B,S,K)
__device__ float2 g_Upk [(D / 2) * D];          // U packed: [p][c] = (U[2p][c], U[2p+1][c])

#define FMA_F32X2(d_, a_, b_, c_) \
    asm("fma.rn.f32x2 %0, %1, %2, %3;" : "=l"(d_) : "l"(a_), "l"(b_), "l"(c_))

// group barrier: 128 threads of row-group g, named barrier id g+1
#define GBAR(g_) asm volatile("bar.sync %0, 128;" :: "r"((g_) + 1) : "memory")

// ---------------------------------------------------------------------------
// Fused: enc_sents[b,s,d] = sum_l emb[prgrph[b,s,l], d]
//        eK[b,s,k]        = sum_d enc[b,s,d] * keys[b,k,d]
// ---------------------------------------------------------------------------
__global__ void gather_eK_kernel(const int* __restrict__ prgrph,
                                 const float* __restrict__ emb,
                                 const float* __restrict__ keys) {
    __shared__ int   sidx[Ln];
    __shared__ float e_sh[D];
    int bs = blockIdx.x;
    int b  = bs / Sn;
    int t  = threadIdx.x;
    int w  = t >> 5, lane = t & 31;
    if (t < Ln) sidx[t] = prgrph[(size_t)bs * Ln + t];
    __syncthreads();
    float acc = 0.f;
#pragma unroll
    for (int l = 0; l < Ln; ++l) acc += __ldg(emb + (size_t)sidx[l] * D + t);
    g_enc[(size_t)bs * D + t] = acc;
    e_sh[t] = acc;
    __syncthreads();
#pragma unroll
    for (int r = 0; r < 4; ++r) {
        int k = w * 4 + r;
        const float* kr = keys + ((size_t)b * Kn + k) * D;
        float p = 0.f;
#pragma unroll
        for (int j = 0; j < 8; ++j) {
            int c = lane + 32 * j;
            p = fmaf(e_sh[c], __ldg(kr + c), p);
        }
#pragma unroll
        for (int o = 16; o > 0; o >>= 1) p += __shfl_xor_sync(0xffffffffu, p, o);
        if (lane == 0) g_eK[(size_t)bs * Kn + k] = p;
    }
}

// ---------------------------------------------------------------------------
__global__ void packU_kernel(const float* __restrict__ U) {
    int p = blockIdx.x;
    int c = threadIdx.x;
    g_Upk[p * D + c] = make_float2(U[(2 * p) * D + c], U[(2 * p + 1) * D + c]);
}

// ---------------------------------------------------------------------------
// 16-row GEMM tile: C[16,D] = A[16,D] @ Bm[D,D]
// ---------------------------------------------------------------------------
__device__ __forceinline__ void gemm16_body(const float* __restrict__ Ab,
                                            const float* __restrict__ Bm,
                                            float* __restrict__ Cb) {
    __shared__ float a_sh[16 * D];
    int t = threadIdx.x;
    for (int i = t; i < 16 * D; i += 256) a_sh[i] = Ab[i];
    __syncthreads();

    float acc[16];
#pragma unroll
    for (int k = 0; k < 16; ++k) acc[k] = 0.f;

    for (int d0 = 0; d0 < D; d0 += 8) {
        float u[8];
#pragma unroll
        for (int i = 0; i < 8; ++i) u[i] = __ldg(Bm + (size_t)(d0 + i) * D + t);
#pragma unroll
        for (int k = 0; k < 16; ++k) {
            float4 h1 = *(const float4*)&a_sh[k * D + d0];
            float4 h2 = *(const float4*)&a_sh[k * D + d0 + 4];
            acc[k] = fmaf(h1.x, u[0], acc[k]); acc[k] = fmaf(h1.y, u[1], acc[k]);
            acc[k] = fmaf(h1.z, u[2], acc[k]); acc[k] = fmaf(h1.w, u[3], acc[k]);
            acc[k] = fmaf(h2.x, u[4], acc[k]); acc[k] = fmaf(h2.y, u[5], acc[k]);
            acc[k] = fmaf(h2.z, u[6], acc[k]); acc[k] = fmaf(h2.w, u[7], acc[k]);
        }
    }
#pragma unroll
    for (int k = 0; k < 16; ++k) Cb[k * D + t] = acc[k];
}

// encW tiles (0..511) + keysV tiles (512..767)
__global__ void gemm_pre_kernel(const float* __restrict__ keys,
                                const float* __restrict__ V,
                                const float* __restrict__ W) {
    int blk = blockIdx.x;
    if (blk < 512) {
        size_t off = (size_t)blk * 16 * D;
        gemm16_body(g_enc + off, W, g_encW + off);
    } else {
        size_t off = (size_t)(blk - 512) * 16 * D;
        gemm16_body(keys + off, V, g_keysV + off);
    }
}

// ---------------------------------------------------------------------------
// The scan. One CTA per batch; 512 threads.
// Thread t: cols (c0=t&127, c1=c0+128); row group g=t>>7 -> rows kb..kb+7.
// Gate/norm rows for warp w: 2w, 2w+1 (always inside own group).
// U streamed cyclically across steps via cp.async double buffering.
// h kept UNNORMALIZED in smem; rs_sh folded into gate/epilogue/output.
// ---------------------------------------------------------------------------
#define CHUNK_PAIRS 32
#define NCHUNK      4
#define CHUNK_BYTES (CHUNK_PAIRS * D * 8)   // 64 KB

__global__ void __launch_bounds__(512, 1)
scan_kernel(const int* __restrict__ pmask,
            float* __restrict__ out) {
    extern __shared__ char smraw[];
    float* h       = (float*)smraw;                         // 32 KB
    char*  ubuf0   = smraw + Kn * D * 4;                    // 64 KB
    char*  ubuf1   = ubuf0 + CHUNK_BYTES;                   // 64 KB
    float* gate_sh = (float*)(ubuf1 + CHUNK_BYTES);         // 32
    float* rs_sh   = gate_sh + Kn;                          // 32
    float* np_sh   = rs_sh + Kn;                            // 32*4 partial sumsq
    int*   smask   = (int*)(np_sh + Kn * 4);                // 64

    const int b    = blockIdx.x;
    const int t    = threadIdx.x;
    const int c0   = t & 127;
    const int c1   = c0 + 128;
    const int g    = t >> 7;
    const int kb   = g * 8;
    const int w    = t >> 5;
    const int wj   = w & 3;
    const int lane = t & 31;

    float hrA[8], hrB[8], kvA[8], kvB[8];
#pragma unroll
    for (int r = 0; r < 8; ++r) {
        hrA[r] = 0.f; hrB[r] = 0.f;
        kvA[r] = g_keysV[((size_t)b * Kn + kb + r) * D + c0];
        kvB[r] = g_keysV[((size_t)b * Kn + kb + r) * D + c1];
    }
    for (int i = t; i < Kn * D; i += 512) h[i] = 0.f;
    if (t < Sn) smask[t] = pmask[((size_t)b * Sn + t) * Ln];
    if (t < Kn) rs_sh[t] = 1.f;
    __syncthreads();

    const char* Usrc = (const char*)g_Upk;

    // initial prefetch of chunk 0 into ubuf0
#pragma unroll
    for (int i = 0; i < 8; ++i) {
        size_t off = (size_t)t * 16 + (size_t)i * 512 * 16;
        __pipeline_memcpy_async(ubuf0 + off, Usrc + off, 16);
    }
    __pipeline_commit();

    const size_t encRow = (size_t)b * Sn;

    for (int s = 0; s < Sn; ++s) {
        if (smask[s] == 0) continue;

        unsigned long long accA[8], accB[8];
#pragma unroll
        for (int r = 0; r < 8; ++r) { accA[r] = 0ull; accB[r] = 0ull; }

#pragma unroll
        for (int ch = 0; ch < NCHUNK; ++ch) {
            __pipeline_wait_prior(0);
            __syncthreads();                       // chunk ch resident; buffers safe
            {   // prefetch chunk (ch+1)&3 into the other buffer (cyclic across steps)
                char* dst = (ch & 1) ? ubuf0 : ubuf1;
                const char* src = Usrc + (size_t)((ch + 1) & 3) * CHUNK_BYTES;
#pragma unroll
                for (int i = 0; i < 8; ++i) {
                    size_t off = (size_t)t * 16 + (size_t)i * 512 * 16;
                    __pipeline_memcpy_async(dst + off, src + off, 16);
                }
                __pipeline_commit();
            }

            if (ch == 0) {
                // gate rows 2w,2w+1: sigmoid(rs*(e.h_raw) + eK); h still old here
                const float* ep = g_enc + (encRow + s) * D;
                float ev[8];
#pragma unroll
                for (int j = 0; j < 8; ++j) ev[j] = __ldg(ep + lane + 32 * j);
#pragma unroll
                for (int r = 0; r < 2; ++r) {
                    int k = 2 * w + r;
                    float p = 0.f;
#pragma unroll
                    for (int j = 0; j < 8; ++j)
                        p = fmaf(ev[j], h[k * D + lane + 32 * j], p);
#pragma unroll
                    for (int o = 16; o > 0; o >>= 1)
                        p += __shfl_xor_sync(0xffffffffu, p, o);
                    if (lane == 0) {
                        float ek = __ldg(g_eK + (encRow + s) * Kn + k);
                        gate_sh[k] = 1.f / (1.f + expf(-(fmaf(rs_sh[k], p, ek))));
                    }
                }
            }

            const unsigned long long* usm =
                (const unsigned long long*)((ch & 1) ? ubuf1 : ubuf0);
            const int dbase = ch * (CHUNK_PAIRS * 2);

            for (int d0l = 0; d0l < CHUNK_PAIRS * 2; d0l += 8) {
                const int pl = d0l >> 1;
                unsigned long long ua0 = usm[(pl + 0) * D + c0];
                unsigned long long ub0 = usm[(pl + 0) * D + c1];
                unsigned long long ua1 = usm[(pl + 1) * D + c0];
                unsigned long long ub1 = usm[(pl + 1) * D + c1];
                unsigned long long ua2 = usm[(pl + 2) * D + c0];
                unsigned long long ub2 = usm[(pl + 2) * D + c1];
                unsigned long long ua3 = usm[(pl + 3) * D + c0];
                unsigned long long ub3 = usm[(pl + 3) * D + c1];
#pragma unroll
                for (int r = 0; r < 8; ++r) {
                    const ulonglong2* hp =
                        (const ulonglong2*)&h[(kb + r) * D + dbase + d0l];
                    ulonglong2 h01 = hp[0];
                    ulonglong2 h23 = hp[1];
                    FMA_F32X2(accA[r], h01.x, ua0, accA[r]);
                    FMA_F32X2(accB[r], h01.x, ub0, accB[r]);
                    FMA_F32X2(accA[r], h01.y, ua1, accA[r]);
                    FMA_F32X2(accB[r], h01.y, ub1, accB[r]);
                    FMA_F32X2(accA[r], h23.x, ua2, accA[r]);
                    FMA_F32X2(accB[r], h23.x, ub2, accB[r]);
                    FMA_F32X2(accA[r], h23.y, ua3, accA[r]);
                    FMA_F32X2(accB[r], h23.y, ub3, accB[r]);
                }
            }
        }

        GBAR(g);   // own group's h reads (gate + GEMM) complete; gate_sh visible

        // epilogue: new h (unnormalized) + register-based norm partials
        const float ewA = __ldg(g_encW + (encRow + s) * D + c0);
        const float ewB = __ldg(g_encW + (encRow + s) * D + c1);
        float np[8];
#pragma unroll
        for (int r = 0; r < 8; ++r) {
            int   k  = kb + r;
            float rs = rs_sh[k];
            float gt = gate_sh[k];
            float2 aA = *(float2*)&accA[r];
            float2 aB = *(float2*)&accB[r];
            float htA = fmaxf(fmaf(rs, aA.x + aA.y, kvA[r] + ewA), 0.f);
            float htB = fmaxf(fmaf(rs, aB.x + aB.y, kvB[r] + ewB), 0.f);
            hrA[r] = fmaf(gt, htA, rs * hrA[r]);
            hrB[r] = fmaf(gt, htB, rs * hrB[r]);
            h[k * D + c0] = hrA[r];
            h[k * D + c1] = hrB[r];
            np[r] = fmaf(hrA[r], hrA[r], hrB[r] * hrB[r]);
        }
#pragma unroll
        for (int o = 16; o > 0; o >>= 1)
#pragma unroll
            for (int r = 0; r < 8; ++r)
                np[r] += __shfl_xor_sync(0xffffffffu, np[r], o);
        if (lane == 0) {
#pragma unroll
            for (int r = 0; r < 8; ++r) np_sh[(kb + r) * 4 + wj] = np[r];
        }

        GBAR(g);   // np_sh ready; also orders next rs_sh write below

        if (wj == 0 && lane < 8) {
            int k = kb + lane;
            float ssum = np_sh[k * 4 + 0] + np_sh[k * 4 + 1] +
                         np_sh[k * 4 + 2] + np_sh[k * 4 + 3];
            rs_sh[k] = rsqrtf(fmaxf(ssum, 1e-12f));
        }
        // rs_sh consumed next step after the chunk-0 global barrier (gate) and
        // after GBAR (epilogue) — both ordered.
    }

    __syncthreads();   // final rs_sh visibility
#pragma unroll
    for (int r = 0; r < 8; ++r) {
        int k = kb + r;
        out[((size_t)b * Kn + k) * D + c0] = hrA[r] * rs_sh[k];
        out[((size_t)b * Kn + k) * D + c1] = hrB[r] * rs_sh[k];
    }
}

// ---------------------------------------------------------------------------
extern "C" void kernel_launch(void* const* d_in, const int* in_sizes, int n_in,
                              void* d_out, int out_size) {
    const int*   prgrph = (const int*)d_in[0];
    const int*   pmask  = (const int*)d_in[1];
    const float* keys   = (const float*)d_in[2];
    const float* emb    = (const float*)d_in[3];
    const float* U      = (const float*)d_in[4];
    const float* V      = (const float*)d_in[5];
    const float* W      = (const float*)d_in[6];
    float*       out    = (float*)d_out;

    const int scan_smem = Kn * D * 4 + 2 * CHUNK_BYTES +
                          (2 * Kn + Kn * 4) * 4 + Sn * 4 + 256;
    cudaFuncSetAttribute(scan_kernel, cudaFuncAttributeMaxDynamicSharedMemorySize,
                         scan_smem);

    gather_eK_kernel<<<Bn * Sn, 256>>>(prgrph, emb, keys);
    packU_kernel<<<D / 2, 256>>>(U);
    gemm_pre_kernel<<<768, 256>>>(keys, V, W);
    scan_kernel<<<Bn, 512, scan_smem>>>(pmask, out);
}